// round 1
// baseline (speedup 1.0000x reference)
#include <cuda_runtime.h>
#include <cuda_bf16.h>
#include <math.h>

// Problem constants
#define Lc 4
#define Bc 16
#define Sc 512
#define Hc 768
#define NHc 12
#define FFc 3072
#define Dc 64
#define Mrows (Bc*Sc)          // 8192
#define BHc (Bc*NHc)           // 192

// ---------------- scratch (device globals; no allocations allowed) -------------
__device__ float g_h [Mrows*Hc];
__device__ float g_y [Mrows*Hc];
__device__ float g_q [Mrows*Hc];
__device__ float g_k [Mrows*Hc];
__device__ float g_v [Mrows*Hc];
__device__ float g_ao[Mrows*Hc];
__device__ float g_sc[(size_t)BHc*Sc*Sc];   // 192*512*512 floats = 201 MB
__device__ float g_ff[Mrows*FFc];           // 100 MB

// ---------------- reductions -------------
__device__ __forceinline__ float warpSum(float v){
#pragma unroll
    for (int o=16;o>0;o>>=1) v += __shfl_xor_sync(0xffffffffu, v, o);
    return v;
}
__device__ __forceinline__ float warpMax(float v){
#pragma unroll
    for (int o=16;o>0;o>>=1) v = fmaxf(v, __shfl_xor_sync(0xffffffffu, v, o));
    return v;
}
__device__ float blockSum(float v){
    __shared__ float sh[8];
    __syncthreads();
    v = warpSum(v);
    int lane = threadIdx.x & 31, w = threadIdx.x >> 5;
    if (lane==0) sh[w] = v;
    __syncthreads();
    int nw = blockDim.x >> 5;
    float r = 0.f;
#pragma unroll 8
    for (int i=0;i<nw;i++) if (i < nw) r += sh[i];
    return r;
}
__device__ float blockMax(float v){
    __shared__ float sh[8];
    __syncthreads();
    v = warpMax(v);
    int lane = threadIdx.x & 31, w = threadIdx.x >> 5;
    if (lane==0) sh[w] = v;
    __syncthreads();
    int nw = blockDim.x >> 5;
    float r = -3.402823466e38f;
#pragma unroll 8
    for (int i=0;i<nw;i++) if (i < nw) r = fmaxf(r, sh[i]);
    return r;
}

// ---------------- LayerNorm: one block per row (H=768, 256 threads, 3 elems/thr) ----
__global__ void ln_kernel(const float* __restrict__ x, const float* __restrict__ g,
                          const float* __restrict__ b, float* __restrict__ o){
    int row = blockIdx.x;
    const float* p = x + (size_t)row*Hc;
    int t = threadIdx.x;
    float v0 = p[t], v1 = p[t+256], v2 = p[t+512];
    float s  = blockSum(v0+v1+v2);
    float m  = s * (1.0f/768.0f);
    float d0 = v0-m, d1 = v1-m, d2 = v2-m;
    float vs = blockSum(d0*d0 + d1*d1 + d2*d2);
    float inv = rsqrtf(vs * (1.0f/768.0f) + 1e-5f);
    float* q = o + (size_t)row*Hc;
    q[t]     = d0*inv*g[t]     + b[t];
    q[t+256] = d1*inv*g[t+256] + b[t+256];
    q[t+512] = d2*inv*g[t+512] + b[t+512];
}

// ---------------- SGEMM 128x128x8, 256 threads, 8x8 microtile -------------
// C[M,N] = A[M,K] @ W[K,N] + bias[N]   (+ GELU | + residual R)
// EPI: 0=bias only, 1=bias+gelu, 2=bias+residual
__device__ __forceinline__ float gelu_exact(float x){
    return 0.5f * x * (1.0f + erff(x * 0.70710678118654752f));
}
template<int EPI>
__global__ void gemm_kernel(const float* __restrict__ A, const float* __restrict__ W,
                            const float* __restrict__ bias, const float* __restrict__ R,
                            float* __restrict__ C, int K, int N){
    __shared__ float As[8][128];
    __shared__ float Bs[8][128];
    int tid = threadIdx.x;
    int bm = blockIdx.y*128, bn = blockIdx.x*128;
    int ar = tid>>1, ac = (tid&1)*4;        // A tile: 128 rows x 8 cols
    int br = tid>>5, bc = (tid&31)*4;       // B tile: 8 rows x 128 cols
    int tm = (tid>>4)*8, tn = (tid&15)*8;
    const float* Ap = A + (size_t)(bm+ar)*K + ac;
    const float* Wp = W + (size_t)br*N + bn + bc;
    float acc[8][8];
#pragma unroll
    for (int i=0;i<8;i++)
#pragma unroll
        for (int j=0;j<8;j++) acc[i][j]=0.f;

    for (int k0=0;k0<K;k0+=8){
        float4 av = *(const float4*)(Ap + k0);
        float4 wv = *(const float4*)(Wp + (size_t)k0*N);
        __syncthreads();
        As[ac+0][ar]=av.x; As[ac+1][ar]=av.y; As[ac+2][ar]=av.z; As[ac+3][ar]=av.w;
        *(float4*)&Bs[br][bc] = wv;
        __syncthreads();
#pragma unroll
        for (int kk=0;kk<8;kk++){
            float a[8], bv[8];
#pragma unroll
            for (int i=0;i<8;i++) a[i]=As[kk][tm+i];
#pragma unroll
            for (int j=0;j<8;j++) bv[j]=Bs[kk][tn+j];
#pragma unroll
            for (int i=0;i<8;i++)
#pragma unroll
                for (int j=0;j<8;j++) acc[i][j] = fmaf(a[i], bv[j], acc[i][j]);
        }
    }
#pragma unroll
    for (int i=0;i<8;i++){
        size_t row = (size_t)(bm+tm+i);
#pragma unroll
        for (int j=0;j<8;j+=4){
            int col = bn+tn+j;
            float4 r;
            r.x = acc[i][j+0] + bias[col+0];
            r.y = acc[i][j+1] + bias[col+1];
            r.z = acc[i][j+2] + bias[col+2];
            r.w = acc[i][j+3] + bias[col+3];
            if (EPI==1){
                r.x = gelu_exact(r.x); r.y = gelu_exact(r.y);
                r.z = gelu_exact(r.z); r.w = gelu_exact(r.w);
            }
            if (EPI==2){
                float4 rr = *(const float4*)(R + row*N + col);
                r.x += rr.x; r.y += rr.y; r.z += rr.z; r.w += rr.w;
            }
            *(float4*)(C + row*N + col) = r;
        }
    }
}

// ---------------- QK^T: per (b,h) 512x512x64, tiles 64x64, fused scale+bias ----
__global__ void attn_qk_kernel(const float* __restrict__ q, const float* __restrict__ k,
                               const float* __restrict__ bias, float* __restrict__ sc){
    __shared__ float Qt[64][64];   // [d][s]
    __shared__ float Kt[64][64];   // [d][t]
    int bh = blockIdx.z;
    int b = bh / NHc, h = bh % NHc;
    int s0 = blockIdx.y*64, t0 = blockIdx.x*64;
    int tid = threadIdx.x;
    int lr = tid>>2;            // 0..63
    int lc = (tid&3)*16;        // 0,16,32,48
    const float* qb = q + ((size_t)(b*Sc + s0 + lr)*NHc + h)*Dc + lc;
    const float* kb = k + ((size_t)(b*Sc + t0 + lr)*NHc + h)*Dc + lc;
#pragma unroll
    for (int z=0; z<4; z++){
        float4 a = *(const float4*)(qb + z*4);
        Qt[lc+z*4+0][lr]=a.x; Qt[lc+z*4+1][lr]=a.y; Qt[lc+z*4+2][lr]=a.z; Qt[lc+z*4+3][lr]=a.w;
        float4 c = *(const float4*)(kb + z*4);
        Kt[lc+z*4+0][lr]=c.x; Kt[lc+z*4+1][lr]=c.y; Kt[lc+z*4+2][lr]=c.z; Kt[lc+z*4+3][lr]=c.w;
    }
    __syncthreads();
    int tm=(tid>>4)*4, tn=(tid&15)*4;
    float acc[4][4];
#pragma unroll
    for (int i=0;i<4;i++)
#pragma unroll
        for (int j=0;j<4;j++) acc[i][j]=0.f;
#pragma unroll 8
    for (int d=0; d<64; d++){
        float a[4], bb[4];
#pragma unroll
        for (int i=0;i<4;i++) a[i]=Qt[d][tm+i];
#pragma unroll
        for (int j=0;j<4;j++) bb[j]=Kt[d][tn+j];
#pragma unroll
        for (int i=0;i<4;i++)
#pragma unroll
            for (int j=0;j<4;j++) acc[i][j] = fmaf(a[i], bb[j], acc[i][j]);
    }
#pragma unroll
    for (int i=0;i<4;i++){
        size_t idx = ((size_t)bh*Sc + (s0+tm+i))*Sc + (t0+tn);
        float4 bi = *(const float4*)(bias + idx);
        float4 r;
        r.x = fmaf(acc[i][0], 0.125f, bi.x);
        r.y = fmaf(acc[i][1], 0.125f, bi.y);
        r.z = fmaf(acc[i][2], 0.125f, bi.z);
        r.w = fmaf(acc[i][3], 0.125f, bi.w);
        *(float4*)(sc + idx) = r;
    }
}

// ---------------- softmax over t (512), one block (128 thr) per row -------------
__global__ void softmax_kernel(float* __restrict__ sc){
    size_t row = blockIdx.x;
    float* p = sc + row*Sc;
    int t = threadIdx.x;
    float v[4];
#pragma unroll
    for (int i=0;i<4;i++) v[i] = p[t + i*128];
    float mx = fmaxf(fmaxf(v[0],v[1]), fmaxf(v[2],v[3]));
    mx = blockMax(mx);
    float s = 0.f;
#pragma unroll
    for (int i=0;i<4;i++){ v[i] = __expf(v[i]-mx); s += v[i]; }
    s = blockSum(s);
    float r = 1.0f / s;
#pragma unroll
    for (int i=0;i<4;i++) p[t + i*128] = v[i]*r;
}

// ---------------- A@V: per (b,h) 512x64x512, tiles 64s x 64d, BK=32 --------------
__global__ void attn_av_kernel(const float* __restrict__ sc, const float* __restrict__ v,
                               float* __restrict__ o){
    __shared__ float At[32][64];   // [t][s]
    __shared__ float Vs[32][64];   // [t][d]
    int bh = blockIdx.y;
    int b = bh / NHc, h = bh % NHc;
    int s0 = blockIdx.x*64;
    int tid = threadIdx.x;
    int ar = tid>>2;            // 0..63 (s rows)
    int ac = (tid&3)*8;         // 0,8,16,24
    int vr = tid>>3;            // 0..31 (t rows)
    int vc = (tid&7)*8;         // 0..56
    int tm=(tid>>4)*4, tn=(tid&15)*4;
    float acc[4][4];
#pragma unroll
    for (int i=0;i<4;i++)
#pragma unroll
        for (int j=0;j<4;j++) acc[i][j]=0.f;

    for (int t0=0; t0<Sc; t0+=32){
        const float* ap = sc + ((size_t)bh*Sc + (s0+ar))*Sc + t0 + ac;
        float4 a0 = *(const float4*)(ap);
        float4 a1 = *(const float4*)(ap + 4);
        const float* vp = v + ((size_t)(b*Sc + t0 + vr)*NHc + h)*Dc + vc;
        float4 w0 = *(const float4*)(vp);
        float4 w1 = *(const float4*)(vp + 4);
        __syncthreads();
        At[ac+0][ar]=a0.x; At[ac+1][ar]=a0.y; At[ac+2][ar]=a0.z; At[ac+3][ar]=a0.w;
        At[ac+4][ar]=a1.x; At[ac+5][ar]=a1.y; At[ac+6][ar]=a1.z; At[ac+7][ar]=a1.w;
        *(float4*)&Vs[vr][vc]   = w0;
        *(float4*)&Vs[vr][vc+4] = w1;
        __syncthreads();
#pragma unroll 8
        for (int kk=0;kk<32;kk++){
            float a[4], bb[4];
#pragma unroll
            for (int i=0;i<4;i++) a[i]=At[kk][tm+i];
#pragma unroll
            for (int j=0;j<4;j++) bb[j]=Vs[kk][tn+j];
#pragma unroll
            for (int i=0;i<4;i++)
#pragma unroll
                for (int j=0;j<4;j++) acc[i][j] = fmaf(a[i], bb[j], acc[i][j]);
        }
    }
#pragma unroll
    for (int i=0;i<4;i++){
        float4 r; r.x=acc[i][0]; r.y=acc[i][1]; r.z=acc[i][2]; r.w=acc[i][3];
        *(float4*)(o + ((size_t)(b*Sc + s0+tm+i)*NHc + h)*Dc + tn) = r;
    }
}

// ---------------- launch -------------
extern "C" void kernel_launch(void* const* d_in, const int* in_sizes, int n_in,
                              void* d_out, int out_size){
    const float* x    = (const float*)d_in[0];
    const float* ab   = (const float*)d_in[1];
    const float* ln1g = (const float*)d_in[2];
    const float* ln1b = (const float*)d_in[3];
    const float* wq   = (const float*)d_in[4];
    const float* bq   = (const float*)d_in[5];
    const float* wk   = (const float*)d_in[6];
    const float* bk   = (const float*)d_in[7];
    const float* wv   = (const float*)d_in[8];
    const float* bv   = (const float*)d_in[9];
    const float* wo   = (const float*)d_in[10];
    const float* bo   = (const float*)d_in[11];
    const float* ln2g = (const float*)d_in[12];
    const float* ln2b = (const float*)d_in[13];
    const float* w1   = (const float*)d_in[14];
    const float* b1   = (const float*)d_in[15];
    const float* w2   = (const float*)d_in[16];
    const float* b2   = (const float*)d_in[17];
    const float* flng = (const float*)d_in[18];
    const float* flnb = (const float*)d_in[19];

    float *ph, *py, *pq, *pk, *pv, *pao, *psc, *pff;
    cudaGetSymbolAddress((void**)&ph,  g_h);
    cudaGetSymbolAddress((void**)&py,  g_y);
    cudaGetSymbolAddress((void**)&pq,  g_q);
    cudaGetSymbolAddress((void**)&pk,  g_k);
    cudaGetSymbolAddress((void**)&pv,  g_v);
    cudaGetSymbolAddress((void**)&pao, g_ao);
    cudaGetSymbolAddress((void**)&psc, g_sc);
    cudaGetSymbolAddress((void**)&pff, g_ff);

    cudaMemcpyAsync(ph, x, (size_t)Mrows*Hc*sizeof(float), cudaMemcpyDeviceToDevice, 0);

    dim3 gproj(Hc/128, Mrows/128);      // 6 x 64
    dim3 gffn1(FFc/128, Mrows/128);     // 24 x 64
    dim3 gqk(8, 8, BHc);
    dim3 gav(8, BHc);

    for (int l=0; l<Lc; l++){
        const float* Wq = wq + (size_t)l*Hc*Hc;
        const float* Wk = wk + (size_t)l*Hc*Hc;
        const float* Wv = wv + (size_t)l*Hc*Hc;
        const float* Wo = wo + (size_t)l*Hc*Hc;
        const float* W1 = w1 + (size_t)l*Hc*FFc;
        const float* W2 = w2 + (size_t)l*FFc*Hc;

        ln_kernel<<<Mrows, 256>>>(ph, ln1g + l*Hc, ln1b + l*Hc, py);
        gemm_kernel<0><<<gproj, 256>>>(py, Wq, bq + l*Hc, nullptr, pq, Hc, Hc);
        gemm_kernel<0><<<gproj, 256>>>(py, Wk, bk + l*Hc, nullptr, pk, Hc, Hc);
        gemm_kernel<0><<<gproj, 256>>>(py, Wv, bv + l*Hc, nullptr, pv, Hc, Hc);
        attn_qk_kernel<<<gqk, 256>>>(pq, pk, ab, psc);
        softmax_kernel<<<BHc*Sc, 128>>>(psc);
        attn_av_kernel<<<gav, 256>>>(psc, pv, pao);
        gemm_kernel<2><<<gproj, 256>>>(pao, Wo, bo + l*Hc, ph, ph, Hc, Hc);
        ln_kernel<<<Mrows, 256>>>(ph, ln2g + l*Hc, ln2b + l*Hc, py);
        gemm_kernel<1><<<gffn1, 256>>>(py, W1, b1 + l*FFc, nullptr, pff, Hc, FFc);
        gemm_kernel<2><<<gproj, 256>>>(pff, W2, b2 + l*Hc, ph, ph, FFc, Hc);
    }
    ln_kernel<<<Mrows, 256>>>(ph, flng, flnb, (float*)d_out);
}

// round 2
// speedup vs baseline: 2.5142x; 2.5142x over previous
#include <cuda_runtime.h>
#include <cuda_bf16.h>
#include <math.h>

// Problem constants
#define Lc 4
#define Bc 16
#define Sc 512
#define Hc 768
#define NHc 12
#define FFc 3072
#define Dc 64
#define Mrows (Bc*Sc)          // 8192
#define BHc (Bc*NHc)           // 192

// ---------------- scratch (device globals; no allocations allowed) -------------
__device__ float g_h [Mrows*Hc];
__device__ float g_y [Mrows*Hc];
__device__ float g_q [Mrows*Hc];
__device__ float g_k [Mrows*Hc];
__device__ float g_v [Mrows*Hc];
__device__ float g_ao[Mrows*Hc];
__device__ float g_sc[(size_t)BHc*Sc*Sc];   // 201 MB
__device__ float g_ff[Mrows*FFc];           // 100 MB

// ---------------- reductions -------------
__device__ __forceinline__ float warpSum(float v){
#pragma unroll
    for (int o=16;o>0;o>>=1) v += __shfl_xor_sync(0xffffffffu, v, o);
    return v;
}
__device__ __forceinline__ float warpMax(float v){
#pragma unroll
    for (int o=16;o>0;o>>=1) v = fmaxf(v, __shfl_xor_sync(0xffffffffu, v, o));
    return v;
}
__device__ float blockSum(float v){
    __shared__ float sh[8];
    __syncthreads();
    v = warpSum(v);
    int lane = threadIdx.x & 31, w = threadIdx.x >> 5;
    if (lane==0) sh[w] = v;
    __syncthreads();
    int nw = blockDim.x >> 5;
    float r = 0.f;
#pragma unroll 8
    for (int i=0;i<nw;i++) if (i < nw) r += sh[i];
    return r;
}
__device__ float blockMax(float v){
    __shared__ float sh[8];
    __syncthreads();
    v = warpMax(v);
    int lane = threadIdx.x & 31, w = threadIdx.x >> 5;
    if (lane==0) sh[w] = v;
    __syncthreads();
    int nw = blockDim.x >> 5;
    float r = -3.402823466e38f;
#pragma unroll 8
    for (int i=0;i<nw;i++) if (i < nw) r = fmaxf(r, sh[i]);
    return r;
}

// ---------------- LayerNorm ----
__global__ void ln_kernel(const float* __restrict__ x, const float* __restrict__ g,
                          const float* __restrict__ b, float* __restrict__ o){
    int row = blockIdx.x;
    const float* p = x + (size_t)row*Hc;
    int t = threadIdx.x;
    float v0 = p[t], v1 = p[t+256], v2 = p[t+512];
    float s  = blockSum(v0+v1+v2);
    float m  = s * (1.0f/768.0f);
    float d0 = v0-m, d1 = v1-m, d2 = v2-m;
    float vs = blockSum(d0*d0 + d1*d1 + d2*d2);
    float inv = rsqrtf(vs * (1.0f/768.0f) + 1e-5f);
    float* q = o + (size_t)row*Hc;
    q[t]     = d0*inv*g[t]     + b[t];
    q[t+256] = d1*inv*g[t+256] + b[t+256];
    q[t+512] = d2*inv*g[t+512] + b[t+512];
}

// ---------------- tf32 MMA helpers -------------
__device__ __forceinline__ unsigned f2tf32(float x){
    unsigned r; asm("cvt.rna.tf32.f32 %0, %1;" : "=r"(r) : "f"(x)); return r;
}
__device__ __forceinline__ void ldsm4(unsigned* d, const float* p){
    unsigned a = (unsigned)__cvta_generic_to_shared(p);
    asm volatile("ldmatrix.sync.aligned.m8n8.x4.shared.b16 {%0,%1,%2,%3}, [%4];"
                 : "=r"(d[0]),"=r"(d[1]),"=r"(d[2]),"=r"(d[3]) : "r"(a));
}
__device__ __forceinline__ void mma_tf32(float* c, const unsigned* a, unsigned b0, unsigned b1){
    asm volatile("mma.sync.aligned.m16n8k8.row.col.f32.tf32.tf32.f32 "
                 "{%0,%1,%2,%3}, {%4,%5,%6,%7}, {%8,%9}, {%0,%1,%2,%3};"
                 : "+f"(c[0]),"+f"(c[1]),"+f"(c[2]),"+f"(c[3])
                 : "r"(a[0]),"r"(a[1]),"r"(a[2]),"r"(a[3]), "r"(b0),"r"(b1));
}
__device__ __forceinline__ float gelu_exact(float x){
    return 0.5f * x * (1.0f + erff(x * 0.70710678118654752f));
}

// ---------------- tf32 tensor-core GEMM 128x128x16, 256 threads -------------
// C[M,N] = A[M,K] @ W[K,N] + bias[N]  (+GELU | +residual)
#define PADt 20
template<int EPI>
__global__ __launch_bounds__(256,2) void mma_gemm(
        const float* __restrict__ A, const float* __restrict__ W,
        const float* __restrict__ bias, const float* __restrict__ R,
        float* __restrict__ C, int K, int N){
    __shared__ float As[2][128*PADt];
    __shared__ float Bs[2][128*PADt];
    int tid = threadIdx.x;
    int bm = blockIdx.y*128, bn = blockIdx.x*128;
    int warp = tid>>5, lane = tid&31;
    int wm = (warp>>2)*64, wn = (warp&3)*32;

    // global A: thread covers row ar, cols [ac, ac+8)
    int ar = tid>>1, ac = (tid&1)*8;
    const float* Ap = A + (size_t)(bm+ar)*K + ac;
    // global B: thread covers n = bnn, k in [bkg, bkg+8)
    int bnn = tid&127, bkg = (tid>>7)*8;
    const float* Wp = W + bn + bnn;

    // ldmatrix lane addressing
    int g = lane>>3, lr = lane&7;
    int a_row = wm + lr + (g&1)*8;          // + mt*16
    int a_colq = (g>>1)*4;                  // + kc
    int b_row = wn + lr + (g>>1)*8;         // + np*16
    int b_colq = (g&1)*4;                   // + kc

    float acc[16][4];
#pragma unroll
    for (int i=0;i<16;i++){ acc[i][0]=0.f; acc[i][1]=0.f; acc[i][2]=0.f; acc[i][3]=0.f; }

    float4 ra0, ra1;
    float rb[8];

    // prologue: load chunk 0
    ra0 = *(const float4*)(Ap);
    ra1 = *(const float4*)(Ap + 4);
#pragma unroll
    for (int j=0;j<8;j++) rb[j] = Wp[(size_t)(bkg+j)*N];
    {
        float* pa = &As[0][ar*PADt + ac];
        pa[0]=__uint_as_float(f2tf32(ra0.x)); pa[1]=__uint_as_float(f2tf32(ra0.y));
        pa[2]=__uint_as_float(f2tf32(ra0.z)); pa[3]=__uint_as_float(f2tf32(ra0.w));
        pa[4]=__uint_as_float(f2tf32(ra1.x)); pa[5]=__uint_as_float(f2tf32(ra1.y));
        pa[6]=__uint_as_float(f2tf32(ra1.z)); pa[7]=__uint_as_float(f2tf32(ra1.w));
        float* pb = &Bs[0][bnn*PADt + bkg];
#pragma unroll
        for (int j=0;j<8;j++) pb[j]=__uint_as_float(f2tf32(rb[j]));
    }
    __syncthreads();

    int nchunks = K >> 4;
    for (int it=0; it<nchunks; it++){
        int buf = it & 1;
        bool has_next = (it+1 < nchunks);
        if (has_next){
            int k0 = (it+1)<<4;
            ra0 = *(const float4*)(Ap + k0);
            ra1 = *(const float4*)(Ap + k0 + 4);
#pragma unroll
            for (int j=0;j<8;j++) rb[j] = Wp[(size_t)(k0+bkg+j)*N];
        }
        // compute on buf
#pragma unroll
        for (int kc=0; kc<16; kc+=8){
            unsigned af[4][4];
#pragma unroll
            for (int mt=0; mt<4; mt++)
                ldsm4(af[mt], &As[buf][(a_row + mt*16)*PADt + kc + a_colq]);
            unsigned bf[2][4];
#pragma unroll
            for (int np=0; np<2; np++)
                ldsm4(bf[np], &Bs[buf][(b_row + np*16)*PADt + kc + b_colq]);
#pragma unroll
            for (int mt=0; mt<4; mt++)
#pragma unroll
                for (int nt=0; nt<4; nt++)
                    mma_tf32(acc[mt*4+nt], af[mt], bf[nt>>1][(nt&1)*2], bf[nt>>1][(nt&1)*2+1]);
        }
        if (has_next){
            int nb = buf ^ 1;
            float* pa = &As[nb][ar*PADt + ac];
            pa[0]=__uint_as_float(f2tf32(ra0.x)); pa[1]=__uint_as_float(f2tf32(ra0.y));
            pa[2]=__uint_as_float(f2tf32(ra0.z)); pa[3]=__uint_as_float(f2tf32(ra0.w));
            pa[4]=__uint_as_float(f2tf32(ra1.x)); pa[5]=__uint_as_float(f2tf32(ra1.y));
            pa[6]=__uint_as_float(f2tf32(ra1.z)); pa[7]=__uint_as_float(f2tf32(ra1.w));
            float* pb = &Bs[nb][bnn*PADt + bkg];
#pragma unroll
            for (int j=0;j<8;j++) pb[j]=__uint_as_float(f2tf32(rb[j]));
            __syncthreads();
        }
    }

    // epilogue
    int cr = lane>>2, cc = (lane&3)*2;
#pragma unroll
    for (int nt=0; nt<4; nt++){
        int col = bn + wn + nt*8 + cc;
        float2 bv = *(const float2*)(bias + col);
#pragma unroll
        for (int mt=0; mt<4; mt++){
            int row0 = bm + wm + mt*16 + cr;
            float* a4 = acc[mt*4+nt];
#pragma unroll
            for (int half=0; half<2; half++){
                int row = row0 + half*8;
                float2 r;
                r.x = a4[half*2+0] + bv.x;
                r.y = a4[half*2+1] + bv.y;
                if (EPI==1){ r.x = gelu_exact(r.x); r.y = gelu_exact(r.y); }
                if (EPI==2){
                    float2 rr = *(const float2*)(R + (size_t)row*N + col);
                    r.x += rr.x; r.y += rr.y;
                }
                *(float2*)(C + (size_t)row*N + col) = r;
            }
        }
    }
}

// ---------------- QK^T: per (b,h) 512x512x64, tiles 64x64, fused scale+bias ----
__global__ void attn_qk_kernel(const float* __restrict__ q, const float* __restrict__ k,
                               const float* __restrict__ bias, float* __restrict__ sc){
    __shared__ float Qt[64][64];
    __shared__ float Kt[64][64];
    int bh = blockIdx.z;
    int b = bh / NHc, h = bh % NHc;
    int s0 = blockIdx.y*64, t0 = blockIdx.x*64;
    int tid = threadIdx.x;
    int lr = tid>>2;
    int lc = (tid&3)*16;
    const float* qb = q + ((size_t)(b*Sc + s0 + lr)*NHc + h)*Dc + lc;
    const float* kb = k + ((size_t)(b*Sc + t0 + lr)*NHc + h)*Dc + lc;
#pragma unroll
    for (int z=0; z<4; z++){
        float4 a = *(const float4*)(qb + z*4);
        Qt[lc+z*4+0][lr]=a.x; Qt[lc+z*4+1][lr]=a.y; Qt[lc+z*4+2][lr]=a.z; Qt[lc+z*4+3][lr]=a.w;
        float4 c = *(const float4*)(kb + z*4);
        Kt[lc+z*4+0][lr]=c.x; Kt[lc+z*4+1][lr]=c.y; Kt[lc+z*4+2][lr]=c.z; Kt[lc+z*4+3][lr]=c.w;
    }
    __syncthreads();
    int tm=(tid>>4)*4, tn=(tid&15)*4;
    float acc[4][4];
#pragma unroll
    for (int i=0;i<4;i++)
#pragma unroll
        for (int j=0;j<4;j++) acc[i][j]=0.f;
#pragma unroll 8
    for (int d=0; d<64; d++){
        float a[4], bb[4];
#pragma unroll
        for (int i=0;i<4;i++) a[i]=Qt[d][tm+i];
#pragma unroll
        for (int j=0;j<4;j++) bb[j]=Kt[d][tn+j];
#pragma unroll
        for (int i=0;i<4;i++)
#pragma unroll
            for (int j=0;j<4;j++) acc[i][j] = fmaf(a[i], bb[j], acc[i][j]);
    }
#pragma unroll
    for (int i=0;i<4;i++){
        size_t idx = ((size_t)bh*Sc + (s0+tm+i))*Sc + (t0+tn);
        float4 bi = *(const float4*)(bias + idx);
        float4 r;
        r.x = fmaf(acc[i][0], 0.125f, bi.x);
        r.y = fmaf(acc[i][1], 0.125f, bi.y);
        r.z = fmaf(acc[i][2], 0.125f, bi.z);
        r.w = fmaf(acc[i][3], 0.125f, bi.w);
        *(float4*)(sc + idx) = r;
    }
}

// ---------------- softmax -------------
__global__ void softmax_kernel(float* __restrict__ sc){
    size_t row = blockIdx.x;
    float* p = sc + row*Sc;
    int t = threadIdx.x;
    float v[4];
#pragma unroll
    for (int i=0;i<4;i++) v[i] = p[t + i*128];
    float mx = fmaxf(fmaxf(v[0],v[1]), fmaxf(v[2],v[3]));
    mx = blockMax(mx);
    float s = 0.f;
#pragma unroll
    for (int i=0;i<4;i++){ v[i] = __expf(v[i]-mx); s += v[i]; }
    s = blockSum(s);
    float r = 1.0f / s;
#pragma unroll
    for (int i=0;i<4;i++) p[t + i*128] = v[i]*r;
}

// ---------------- A@V -------------
__global__ void attn_av_kernel(const float* __restrict__ sc, const float* __restrict__ v,
                               float* __restrict__ o){
    __shared__ float At[32][64];
    __shared__ float Vs[32][64];
    int bh = blockIdx.y;
    int b = bh / NHc, h = bh % NHc;
    int s0 = blockIdx.x*64;
    int tid = threadIdx.x;
    int ar = tid>>2;
    int ac = (tid&3)*8;
    int vr = tid>>3;
    int vc = (tid&7)*8;
    int tm=(tid>>4)*4, tn=(tid&15)*4;
    float acc[4][4];
#pragma unroll
    for (int i=0;i<4;i++)
#pragma unroll
        for (int j=0;j<4;j++) acc[i][j]=0.f;

    for (int t0=0; t0<Sc; t0+=32){
        const float* ap = sc + ((size_t)bh*Sc + (s0+ar))*Sc + t0 + ac;
        float4 a0 = *(const float4*)(ap);
        float4 a1 = *(const float4*)(ap + 4);
        const float* vp = v + ((size_t)(b*Sc + t0 + vr)*NHc + h)*Dc + vc;
        float4 w0 = *(const float4*)(vp);
        float4 w1 = *(const float4*)(vp + 4);
        __syncthreads();
        At[ac+0][ar]=a0.x; At[ac+1][ar]=a0.y; At[ac+2][ar]=a0.z; At[ac+3][ar]=a0.w;
        At[ac+4][ar]=a1.x; At[ac+5][ar]=a1.y; At[ac+6][ar]=a1.z; At[ac+7][ar]=a1.w;
        *(float4*)&Vs[vr][vc]   = w0;
        *(float4*)&Vs[vr][vc+4] = w1;
        __syncthreads();
#pragma unroll 8
        for (int kk=0;kk<32;kk++){
            float a[4], bb[4];
#pragma unroll
            for (int i=0;i<4;i++) a[i]=At[kk][tm+i];
#pragma unroll
            for (int j=0;j<4;j++) bb[j]=Vs[kk][tn+j];
#pragma unroll
            for (int i=0;i<4;i++)
#pragma unroll
                for (int j=0;j<4;j++) acc[i][j] = fmaf(a[i], bb[j], acc[i][j]);
        }
    }
#pragma unroll
    for (int i=0;i<4;i++){
        float4 r; r.x=acc[i][0]; r.y=acc[i][1]; r.z=acc[i][2]; r.w=acc[i][3];
        *(float4*)(o + ((size_t)(b*Sc + s0+tm+i)*NHc + h)*Dc + tn) = r;
    }
}

// ---------------- launch -------------
extern "C" void kernel_launch(void* const* d_in, const int* in_sizes, int n_in,
                              void* d_out, int out_size){
    const float* x    = (const float*)d_in[0];
    const float* ab   = (const float*)d_in[1];
    const float* ln1g = (const float*)d_in[2];
    const float* ln1b = (const float*)d_in[3];
    const float* wq   = (const float*)d_in[4];
    const float* bq   = (const float*)d_in[5];
    const float* wk   = (const float*)d_in[6];
    const float* bk   = (const float*)d_in[7];
    const float* wv   = (const float*)d_in[8];
    const float* bv   = (const float*)d_in[9];
    const float* wo   = (const float*)d_in[10];
    const float* bo   = (const float*)d_in[11];
    const float* ln2g = (const float*)d_in[12];
    const float* ln2b = (const float*)d_in[13];
    const float* w1   = (const float*)d_in[14];
    const float* b1   = (const float*)d_in[15];
    const float* w2   = (const float*)d_in[16];
    const float* b2   = (const float*)d_in[17];
    const float* flng = (const float*)d_in[18];
    const float* flnb = (const float*)d_in[19];

    float *ph, *py, *pq, *pk, *pv, *pao, *psc, *pff;
    cudaGetSymbolAddress((void**)&ph,  g_h);
    cudaGetSymbolAddress((void**)&py,  g_y);
    cudaGetSymbolAddress((void**)&pq,  g_q);
    cudaGetSymbolAddress((void**)&pk,  g_k);
    cudaGetSymbolAddress((void**)&pv,  g_v);
    cudaGetSymbolAddress((void**)&pao, g_ao);
    cudaGetSymbolAddress((void**)&psc, g_sc);
    cudaGetSymbolAddress((void**)&pff, g_ff);

    cudaMemcpyAsync(ph, x, (size_t)Mrows*Hc*sizeof(float), cudaMemcpyDeviceToDevice, 0);

    dim3 gproj(Hc/128, Mrows/128);      // 6 x 64
    dim3 gffn1(FFc/128, Mrows/128);     // 24 x 64
    dim3 gqk(8, 8, BHc);
    dim3 gav(8, BHc);

    for (int l=0; l<Lc; l++){
        const float* Wq = wq + (size_t)l*Hc*Hc;
        const float* Wk = wk + (size_t)l*Hc*Hc;
        const float* Wv = wv + (size_t)l*Hc*Hc;
        const float* Wo = wo + (size_t)l*Hc*Hc;
        const float* W1 = w1 + (size_t)l*Hc*FFc;
        const float* W2 = w2 + (size_t)l*FFc*Hc;

        ln_kernel<<<Mrows, 256>>>(ph, ln1g + l*Hc, ln1b + l*Hc, py);
        mma_gemm<0><<<gproj, 256>>>(py, Wq, bq + l*Hc, nullptr, pq, Hc, Hc);
        mma_gemm<0><<<gproj, 256>>>(py, Wk, bk + l*Hc, nullptr, pk, Hc, Hc);
        mma_gemm<0><<<gproj, 256>>>(py, Wv, bv + l*Hc, nullptr, pv, Hc, Hc);
        attn_qk_kernel<<<gqk, 256>>>(pq, pk, ab, psc);
        softmax_kernel<<<BHc*Sc, 128>>>(psc);
        attn_av_kernel<<<gav, 256>>>(psc, pv, pao);
        mma_gemm<2><<<gproj, 256>>>(pao, Wo, bo + l*Hc, ph, ph, Hc, Hc);
        ln_kernel<<<Mrows, 256>>>(ph, ln2g + l*Hc, ln2b + l*Hc, py);
        mma_gemm<1><<<gffn1, 256>>>(py, W1, b1 + l*FFc, nullptr, pff, Hc, FFc);
        mma_gemm<2><<<gproj, 256>>>(pff, W2, b2 + l*Hc, ph, ph, FFc, Hc);
    }
    ln_kernel<<<Mrows, 256>>>(ph, flng, flnb, (float*)d_out);
}

// round 6
// speedup vs baseline: 2.8263x; 1.1241x over previous
#include <cuda_runtime.h>
#include <cuda_bf16.h>
#include <math.h>

// Problem constants
#define Lc 4
#define Bc 16
#define Sc 512
#define Hc 768
#define NHc 12
#define FFc 3072
#define Dc 64
#define Mrows (Bc*Sc)          // 8192
#define BHc (Bc*NHc)           // 192

// ---------------- scratch (device globals; no allocations allowed) -------------
__device__ float g_h [Mrows*Hc];
__device__ float g_y [Mrows*Hc];
__device__ float g_q [Mrows*Hc];
__device__ float g_k [Mrows*Hc];
__device__ float g_v [Mrows*Hc];
__device__ float g_ao[Mrows*Hc];
__device__ float g_sc[(size_t)BHc*Sc*Sc];   // 201 MB
__device__ float g_ff[Mrows*FFc];           // 100 MB

// ---------------- reductions -------------
__device__ __forceinline__ float warpSum(float v){
#pragma unroll
    for (int o=16;o>0;o>>=1) v += __shfl_xor_sync(0xffffffffu, v, o);
    return v;
}
__device__ __forceinline__ float warpMax(float v){
#pragma unroll
    for (int o=16;o>0;o>>=1) v = fmaxf(v, __shfl_xor_sync(0xffffffffu, v, o));
    return v;
}
__device__ float blockSum(float v){
    __shared__ float sh[8];
    __syncthreads();
    v = warpSum(v);
    int lane = threadIdx.x & 31, w = threadIdx.x >> 5;
    if (lane==0) sh[w] = v;
    __syncthreads();
    int nw = blockDim.x >> 5;
    float r = 0.f;
#pragma unroll 8
    for (int i=0;i<nw;i++) if (i < nw) r += sh[i];
    return r;
}
__device__ float blockMax(float v){
    __shared__ float sh[8];
    __syncthreads();
    v = warpMax(v);
    int lane = threadIdx.x & 31, w = threadIdx.x >> 5;
    if (lane==0) sh[w] = v;
    __syncthreads();
    int nw = blockDim.x >> 5;
    float r = -3.402823466e38f;
#pragma unroll 8
    for (int i=0;i<nw;i++) if (i < nw) r = fmaxf(r, sh[i]);
    return r;
}

// ---------------- LayerNorm ----
__global__ void ln_kernel(const float* __restrict__ x, const float* __restrict__ g,
                          const float* __restrict__ b, float* __restrict__ o){
    int row = blockIdx.x;
    const float* p = x + (size_t)row*Hc;
    int t = threadIdx.x;
    float v0 = p[t], v1 = p[t+256], v2 = p[t+512];
    float s  = blockSum(v0+v1+v2);
    float m  = s * (1.0f/768.0f);
    float d0 = v0-m, d1 = v1-m, d2 = v2-m;
    float vs = blockSum(d0*d0 + d1*d1 + d2*d2);
    float inv = rsqrtf(vs * (1.0f/768.0f) + 1e-5f);
    float* q = o + (size_t)row*Hc;
    q[t]     = d0*inv*g[t]     + b[t];
    q[t+256] = d1*inv*g[t+256] + b[t+256];
    q[t+512] = d2*inv*g[t+512] + b[t+512];
}

// ---------------- tf32 MMA helpers -------------
__device__ __forceinline__ unsigned f2tf32(float x){
    unsigned r; asm("cvt.rna.tf32.f32 %0, %1;" : "=r"(r) : "f"(x)); return r;
}
__device__ __forceinline__ void ldsm4(unsigned* d, const float* p){
    unsigned a = (unsigned)__cvta_generic_to_shared(p);
    asm volatile("ldmatrix.sync.aligned.m8n8.x4.shared.b16 {%0,%1,%2,%3}, [%4];"
                 : "=r"(d[0]),"=r"(d[1]),"=r"(d[2]),"=r"(d[3]) : "r"(a));
}
__device__ __forceinline__ void mma_tf32(float* c, const unsigned* a, unsigned b0, unsigned b1){
    asm volatile("mma.sync.aligned.m16n8k8.row.col.f32.tf32.tf32.f32 "
                 "{%0,%1,%2,%3}, {%4,%5,%6,%7}, {%8,%9}, {%0,%1,%2,%3};"
                 : "+f"(c[0]),"+f"(c[1]),"+f"(c[2]),"+f"(c[3])
                 : "r"(a[0]),"r"(a[1]),"r"(a[2]),"r"(a[3]), "r"(b0),"r"(b1));
}
__device__ __forceinline__ float gelu_exact(float x){
    return 0.5f * x * (1.0f + erff(x * 0.70710678118654752f));
}

// ---------------- tf32 tensor-core GEMM 128x128x16, 256 threads -------------
#define PADt 20
template<int EPI>
__global__ __launch_bounds__(256,2) void mma_gemm(
        const float* __restrict__ A, const float* __restrict__ W,
        const float* __restrict__ bias, const float* __restrict__ R,
        float* __restrict__ C, int K, int N){
    __shared__ float As[2][128*PADt];
    __shared__ float Bs[2][128*PADt];
    int tid = threadIdx.x;
    int bm = blockIdx.y*128, bn = blockIdx.x*128;
    int warp = tid>>5, lane = tid&31;
    int wm = (warp>>2)*64, wn = (warp&3)*32;

    int ar = tid>>1, ac = (tid&1)*8;
    const float* Ap = A + (size_t)(bm+ar)*K + ac;
    int bnn = tid&127, bkg = (tid>>7)*8;
    const float* Wp = W + bn + bnn;

    int g = lane>>3, lr = lane&7;
    int a_row = wm + lr + (g&1)*8;
    int a_colq = (g>>1)*4;
    int b_row = wn + lr + (g>>1)*8;
    int b_colq = (g&1)*4;

    float acc[16][4];
#pragma unroll
    for (int i=0;i<16;i++){ acc[i][0]=0.f; acc[i][1]=0.f; acc[i][2]=0.f; acc[i][3]=0.f; }

    float4 ra0, ra1;
    float rb[8];

    ra0 = *(const float4*)(Ap);
    ra1 = *(const float4*)(Ap + 4);
#pragma unroll
    for (int j=0;j<8;j++) rb[j] = Wp[(size_t)(bkg+j)*N];
    {
        float* pa = &As[0][ar*PADt + ac];
        pa[0]=__uint_as_float(f2tf32(ra0.x)); pa[1]=__uint_as_float(f2tf32(ra0.y));
        pa[2]=__uint_as_float(f2tf32(ra0.z)); pa[3]=__uint_as_float(f2tf32(ra0.w));
        pa[4]=__uint_as_float(f2tf32(ra1.x)); pa[5]=__uint_as_float(f2tf32(ra1.y));
        pa[6]=__uint_as_float(f2tf32(ra1.z)); pa[7]=__uint_as_float(f2tf32(ra1.w));
        float* pb = &Bs[0][bnn*PADt + bkg];
#pragma unroll
        for (int j=0;j<8;j++) pb[j]=__uint_as_float(f2tf32(rb[j]));
    }
    __syncthreads();

    int nchunks = K >> 4;
    for (int it=0; it<nchunks; it++){
        int buf = it & 1;
        bool has_next = (it+1 < nchunks);
        if (has_next){
            int k0 = (it+1)<<4;
            ra0 = *(const float4*)(Ap + k0);
            ra1 = *(const float4*)(Ap + k0 + 4);
#pragma unroll
            for (int j=0;j<8;j++) rb[j] = Wp[(size_t)(k0+bkg+j)*N];
        }
#pragma unroll
        for (int kc=0; kc<16; kc+=8){
            unsigned af[4][4];
#pragma unroll
            for (int mt=0; mt<4; mt++)
                ldsm4(af[mt], &As[buf][(a_row + mt*16)*PADt + kc + a_colq]);
            unsigned bf[2][4];
#pragma unroll
            for (int np=0; np<2; np++)
                ldsm4(bf[np], &Bs[buf][(b_row + np*16)*PADt + kc + b_colq]);
#pragma unroll
            for (int mt=0; mt<4; mt++)
#pragma unroll
                for (int nt=0; nt<4; nt++)
                    mma_tf32(acc[mt*4+nt], af[mt], bf[nt>>1][(nt&1)*2], bf[nt>>1][(nt&1)*2+1]);
        }
        if (has_next){
            int nb = buf ^ 1;
            float* pa = &As[nb][ar*PADt + ac];
            pa[0]=__uint_as_float(f2tf32(ra0.x)); pa[1]=__uint_as_float(f2tf32(ra0.y));
            pa[2]=__uint_as_float(f2tf32(ra0.z)); pa[3]=__uint_as_float(f2tf32(ra0.w));
            pa[4]=__uint_as_float(f2tf32(ra1.x)); pa[5]=__uint_as_float(f2tf32(ra1.y));
            pa[6]=__uint_as_float(f2tf32(ra1.z)); pa[7]=__uint_as_float(f2tf32(ra1.w));
            float* pb = &Bs[nb][bnn*PADt + bkg];
#pragma unroll
            for (int j=0;j<8;j++) pb[j]=__uint_as_float(f2tf32(rb[j]));
            __syncthreads();
        }
    }

    int cr = lane>>2, cc = (lane&3)*2;
#pragma unroll
    for (int nt=0; nt<4; nt++){
        int col = bn + wn + nt*8 + cc;
        float2 bv = *(const float2*)(bias + col);
#pragma unroll
        for (int mt=0; mt<4; mt++){
            int row0 = bm + wm + mt*16 + cr;
            float* a4 = acc[mt*4+nt];
#pragma unroll
            for (int half=0; half<2; half++){
                int row = row0 + half*8;
                float2 r;
                r.x = a4[half*2+0] + bv.x;
                r.y = a4[half*2+1] + bv.y;
                if (EPI==1){ r.x = gelu_exact(r.x); r.y = gelu_exact(r.y); }
                if (EPI==2){
                    float2 rr = *(const float2*)(R + (size_t)row*N + col);
                    r.x += rr.x; r.y += rr.y;
                }
                *(float2*)(C + (size_t)row*N + col) = r;
            }
        }
    }
}

// ---------------- tf32 QK^T: 128x128 tile, K=64, fused scale+bias ----
#define PADQ 68
__global__ __launch_bounds__(256,2) void attn_qk_mma(
        const float* __restrict__ q, const float* __restrict__ k,
        const float* __restrict__ bias, float* __restrict__ sc){
    extern __shared__ float sm[];
    float* Qs = sm;                 // [128][PADQ]
    float* Ks = sm + 128*PADQ;      // [128][PADQ]
    int bh = blockIdx.z;
    int b = bh / NHc, h = bh % NHc;
    int s0 = blockIdx.y*128, t0 = blockIdx.x*128;
    int tid = threadIdx.x;
    int warp = tid>>5, lane = tid&31;
    int wm = (warp>>2)*64, wn = (warp&3)*32;

    // load Q and K tiles (row = tid>>1, 32 cols each half)
    {
        int row = tid>>1, cb = (tid&1)*32;
        const float* qp = q + ((size_t)(b*Sc + s0 + row)*NHc + h)*Dc + cb;
        const float* kp = k + ((size_t)(b*Sc + t0 + row)*NHc + h)*Dc + cb;
        float* dq = &Qs[row*PADQ + cb];
        float* dk = &Ks[row*PADQ + cb];
#pragma unroll
        for (int z=0; z<8; z++){
            float4 a = *(const float4*)(qp + z*4);
            dq[z*4+0]=__uint_as_float(f2tf32(a.x)); dq[z*4+1]=__uint_as_float(f2tf32(a.y));
            dq[z*4+2]=__uint_as_float(f2tf32(a.z)); dq[z*4+3]=__uint_as_float(f2tf32(a.w));
            float4 c = *(const float4*)(kp + z*4);
            dk[z*4+0]=__uint_as_float(f2tf32(c.x)); dk[z*4+1]=__uint_as_float(f2tf32(c.y));
            dk[z*4+2]=__uint_as_float(f2tf32(c.z)); dk[z*4+3]=__uint_as_float(f2tf32(c.w));
        }
    }
    __syncthreads();

    int g = lane>>3, lr = lane&7;
    int a_row = wm + lr + (g&1)*8;
    int a_colq = (g>>1)*4;
    int b_row = wn + lr + (g>>1)*8;
    int b_colq = (g&1)*4;

    float acc[16][4];
#pragma unroll
    for (int i=0;i<16;i++){ acc[i][0]=0.f; acc[i][1]=0.f; acc[i][2]=0.f; acc[i][3]=0.f; }

#pragma unroll
    for (int kc=0; kc<64; kc+=8){
        unsigned af[4][4];
#pragma unroll
        for (int mt=0; mt<4; mt++)
            ldsm4(af[mt], &Qs[(a_row + mt*16)*PADQ + kc + a_colq]);
        unsigned bf[2][4];
#pragma unroll
        for (int np=0; np<2; np++)
            ldsm4(bf[np], &Ks[(b_row + np*16)*PADQ + kc + b_colq]);
#pragma unroll
        for (int mt=0; mt<4; mt++)
#pragma unroll
            for (int nt=0; nt<4; nt++)
                mma_tf32(acc[mt*4+nt], af[mt], bf[nt>>1][(nt&1)*2], bf[nt>>1][(nt&1)*2+1]);
    }

    int cr = lane>>2, cc = (lane&3)*2;
#pragma unroll
    for (int nt=0; nt<4; nt++){
        int tcol = t0 + wn + nt*8 + cc;
#pragma unroll
        for (int mt=0; mt<4; mt++){
            float* a4 = acc[mt*4+nt];
#pragma unroll
            for (int half=0; half<2; half++){
                int srow = s0 + wm + mt*16 + cr + half*8;
                size_t idx = ((size_t)bh*Sc + srow)*Sc + tcol;
                float2 bi = *(const float2*)(bias + idx);
                float2 r;
                r.x = fmaf(a4[half*2+0], 0.125f, bi.x);
                r.y = fmaf(a4[half*2+1], 0.125f, bi.y);
                *(float2*)(sc + idx) = r;
            }
        }
    }
}

// ---------------- softmax -------------
__global__ void softmax_kernel(float* __restrict__ sc){
    size_t row = blockIdx.x;
    float* p = sc + row*Sc;
    int t = threadIdx.x;
    float v[4];
#pragma unroll
    for (int i=0;i<4;i++) v[i] = p[t + i*128];
    float mx = fmaxf(fmaxf(v[0],v[1]), fmaxf(v[2],v[3]));
    mx = blockMax(mx);
    float s = 0.f;
#pragma unroll
    for (int i=0;i<4;i++){ v[i] = __expf(v[i]-mx); s += v[i]; }
    s = blockSum(s);
    float r = 1.0f / s;
#pragma unroll
    for (int i=0;i<4;i++) p[t + i*128] = v[i]*r;
}

// ---------------- tf32 A@V: 128(s) x 64(d), K=512 in chunks of 64 ----
__global__ __launch_bounds__(256,2) void attn_av_mma(
        const float* __restrict__ sc, const float* __restrict__ v,
        float* __restrict__ o){
    extern __shared__ float sm[];
    float* As = sm;                 // [128][PADQ]  (P tile, [s][t])
    float* Vs = sm + 128*PADQ;      // [64][PADQ]   (V tile, [d][t] transposed)
    int bh = blockIdx.y;
    int b = bh / NHc, h = bh % NHc;
    int s0 = blockIdx.x*128;
    int tid = threadIdx.x;
    int warp = tid>>5, lane = tid&31;
    int wm = (warp>>1)*32, wn = (warp&1)*32;

    int g = lane>>3, lr = lane&7;
    int a_row = wm + lr + (g&1)*8;
    int a_colq = (g>>1)*4;
    int b_row = wn + lr + (g>>1)*8;
    int b_colq = (g&1)*4;

    float acc[8][4];
#pragma unroll
    for (int i=0;i<8;i++){ acc[i][0]=0.f; acc[i][1]=0.f; acc[i][2]=0.f; acc[i][3]=0.f; }

    int prow = tid>>1, pcb = (tid&1)*32;
    int vt = tid>>2, vdb = (tid&3)*16;

    for (int t0c=0; t0c<Sc; t0c+=64){
        // P tile: [s][t]
        const float* pp = sc + ((size_t)bh*Sc + (s0+prow))*Sc + t0c + pcb;
        // V tile transposed: [d][t]
        const float* vp = v + ((size_t)(b*Sc + t0c + vt)*NHc + h)*Dc + vdb;
        float4 pv[8], vv[4];
#pragma unroll
        for (int z=0; z<8; z++) pv[z] = *(const float4*)(pp + z*4);
#pragma unroll
        for (int z=0; z<4; z++) vv[z] = *(const float4*)(vp + z*4);
        __syncthreads();
        float* dp = &As[prow*PADQ + pcb];
#pragma unroll
        for (int z=0; z<8; z++){
            dp[z*4+0]=__uint_as_float(f2tf32(pv[z].x)); dp[z*4+1]=__uint_as_float(f2tf32(pv[z].y));
            dp[z*4+2]=__uint_as_float(f2tf32(pv[z].z)); dp[z*4+3]=__uint_as_float(f2tf32(pv[z].w));
        }
#pragma unroll
        for (int z=0; z<4; z++){
            Vs[(vdb+z*4+0)*PADQ + vt]=__uint_as_float(f2tf32(vv[z].x));
            Vs[(vdb+z*4+1)*PADQ + vt]=__uint_as_float(f2tf32(vv[z].y));
            Vs[(vdb+z*4+2)*PADQ + vt]=__uint_as_float(f2tf32(vv[z].z));
            Vs[(vdb+z*4+3)*PADQ + vt]=__uint_as_float(f2tf32(vv[z].w));
        }
        __syncthreads();
#pragma unroll
        for (int kc=0; kc<64; kc+=8){
            unsigned af[2][4];
#pragma unroll
            for (int mt=0; mt<2; mt++)
                ldsm4(af[mt], &As[(a_row + mt*16)*PADQ + kc + a_colq]);
            unsigned bf[2][4];
#pragma unroll
            for (int np=0; np<2; np++)
                ldsm4(bf[np], &Vs[(b_row + np*16)*PADQ + kc + b_colq]);
#pragma unroll
            for (int mt=0; mt<2; mt++)
#pragma unroll
                for (int nt=0; nt<4; nt++)
                    mma_tf32(acc[mt*4+nt], af[mt], bf[nt>>1][(nt&1)*2], bf[nt>>1][(nt&1)*2+1]);
        }
    }

    int cr = lane>>2, cc = (lane&3)*2;
#pragma unroll
    for (int nt=0; nt<4; nt++){
        int dcol = wn + nt*8 + cc;
#pragma unroll
        for (int mt=0; mt<2; mt++){
            float* a4 = acc[mt*4+nt];
#pragma unroll
            for (int half=0; half<2; half++){
                int srow = s0 + wm + mt*16 + cr + half*8;
                float2 r; r.x = a4[half*2+0]; r.y = a4[half*2+1];
                *(float2*)(o + ((size_t)(b*Sc + srow)*NHc + h)*Dc + dcol) = r;
            }
        }
    }
}

// ---------------- launch -------------
extern "C" void kernel_launch(void* const* d_in, const int* in_sizes, int n_in,
                              void* d_out, int out_size){
    const float* x    = (const float*)d_in[0];
    const float* ab   = (const float*)d_in[1];
    const float* ln1g = (const float*)d_in[2];
    const float* ln1b = (const float*)d_in[3];
    const float* wq   = (const float*)d_in[4];
    const float* bq   = (const float*)d_in[5];
    const float* wk   = (const float*)d_in[6];
    const float* bk   = (const float*)d_in[7];
    const float* wv   = (const float*)d_in[8];
    const float* bv   = (const float*)d_in[9];
    const float* wo   = (const float*)d_in[10];
    const float* bo   = (const float*)d_in[11];
    const float* ln2g = (const float*)d_in[12];
    const float* ln2b = (const float*)d_in[13];
    const float* w1   = (const float*)d_in[14];
    const float* b1   = (const float*)d_in[15];
    const float* w2   = (const float*)d_in[16];
    const float* b2   = (const float*)d_in[17];
    const float* flng = (const float*)d_in[18];
    const float* flnb = (const float*)d_in[19];

    float *ph, *py, *pq, *pk, *pv, *pao, *psc, *pff;
    cudaGetSymbolAddress((void**)&ph,  g_h);
    cudaGetSymbolAddress((void**)&py,  g_y);
    cudaGetSymbolAddress((void**)&pq,  g_q);
    cudaGetSymbolAddress((void**)&pk,  g_k);
    cudaGetSymbolAddress((void**)&pv,  g_v);
    cudaGetSymbolAddress((void**)&pao, g_ao);
    cudaGetSymbolAddress((void**)&psc, g_sc);
    cudaGetSymbolAddress((void**)&pff, g_ff);

    static int smem_set = 0;
    const int qk_smem = 2*128*PADQ*sizeof(float);          // 69632
    const int av_smem = (128+64)*PADQ*sizeof(float);       // 52224
    if (!smem_set){
        cudaFuncSetAttribute(attn_qk_mma, cudaFuncAttributeMaxDynamicSharedMemorySize, qk_smem);
        cudaFuncSetAttribute(attn_av_mma, cudaFuncAttributeMaxDynamicSharedMemorySize, av_smem);
        smem_set = 1;
    }

    cudaMemcpyAsync(ph, x, (size_t)Mrows*Hc*sizeof(float), cudaMemcpyDeviceToDevice, 0);

    dim3 gproj(Hc/128, Mrows/128);      // 6 x 64
    dim3 gffn1(FFc/128, Mrows/128);     // 24 x 64
    dim3 gqk(4, 4, BHc);
    dim3 gav(4, BHc);

    for (int l=0; l<Lc; l++){
        const float* Wq = wq + (size_t)l*Hc*Hc;
        const float* Wk = wk + (size_t)l*Hc*Hc;
        const float* Wv = wv + (size_t)l*Hc*Hc;
        const float* Wo = wo + (size_t)l*Hc*Hc;
        const float* W1 = w1 + (size_t)l*Hc*FFc;
        const float* W2 = w2 + (size_t)l*FFc*Hc;

        ln_kernel<<<Mrows, 256>>>(ph, ln1g + l*Hc, ln1b + l*Hc, py);
        mma_gemm<0><<<gproj, 256>>>(py, Wq, bq + l*Hc, nullptr, pq, Hc, Hc);
        mma_gemm<0><<<gproj, 256>>>(py, Wk, bk + l*Hc, nullptr, pk, Hc, Hc);
        mma_gemm<0><<<gproj, 256>>>(py, Wv, bv + l*Hc, nullptr, pv, Hc, Hc);
        attn_qk_mma<<<gqk, 256, qk_smem>>>(pq, pk, ab, psc);
        softmax_kernel<<<BHc*Sc, 128>>>(psc);
        attn_av_mma<<<gav, 256, av_smem>>>(psc, pv, pao);
        mma_gemm<2><<<gproj, 256>>>(pao, Wo, bo + l*Hc, ph, ph, Hc, Hc);
        ln_kernel<<<Mrows, 256>>>(ph, ln2g + l*Hc, ln2b + l*Hc, py);
        mma_gemm<1><<<gffn1, 256>>>(py, W1, b1 + l*FFc, nullptr, pff, Hc, FFc);
        mma_gemm<2><<<gproj, 256>>>(pff, W2, b2 + l*Hc, ph, ph, FFc, Hc);
    }
    ln_kernel<<<Mrows, 256>>>(ph, flng, flnb, (float*)d_out);
}

// round 11
// speedup vs baseline: 2.9852x; 1.0562x over previous
#include <cuda_runtime.h>
#include <cuda_bf16.h>
#include <math.h>

// Problem constants
#define Lc 4
#define Bc 16
#define Sc 512
#define Hc 768
#define NHc 12
#define FFc 3072
#define Dc 64
#define Mrows (Bc*Sc)          // 8192
#define BHc (Bc*NHc)           // 192
#define QKVS 2304              // packed qkv row stride

// ---------------- scratch (device globals; no allocations allowed) -------------
__device__ float g_h [Mrows*Hc];
__device__ float g_y [Mrows*Hc];
__device__ float g_ao[Mrows*Hc];
__device__ float g_sc[(size_t)BHc*Sc*Sc];   // 201 MB
__device__ float g_ff[(size_t)Mrows*FFc];   // 100 MB (also holds packed qkv early in layer)
__device__ float g_wqkvT[(size_t)Lc*3*Hc*Hc];  // [L][2304][768]
__device__ float g_woT  [(size_t)Lc*Hc*Hc];    // [L][768][768]
__device__ float g_w1T  [(size_t)Lc*FFc*Hc];   // [L][3072][768]
__device__ float g_w2T  [(size_t)Lc*Hc*FFc];   // [L][768][3072]
__device__ float g_bqkv [Lc*3*Hc];

// ---------------- reductions -------------
__device__ __forceinline__ float warpSum(float v){
#pragma unroll
    for (int o=16;o>0;o>>=1) v += __shfl_xor_sync(0xffffffffu, v, o);
    return v;
}
__device__ __forceinline__ float warpMax(float v){
#pragma unroll
    for (int o=16;o>0;o>>=1) v = fmaxf(v, __shfl_xor_sync(0xffffffffu, v, o));
    return v;
}
__device__ float blockSum(float v){
    __shared__ float sh[8];
    __syncthreads();
    v = warpSum(v);
    int lane = threadIdx.x & 31, w = threadIdx.x >> 5;
    if (lane==0) sh[w] = v;
    __syncthreads();
    int nw = blockDim.x >> 5;
    float r = 0.f;
#pragma unroll 8
    for (int i=0;i<nw;i++) if (i < nw) r += sh[i];
    return r;
}
__device__ float blockMax(float v){
    __shared__ float sh[8];
    __syncthreads();
    v = warpMax(v);
    int lane = threadIdx.x & 31, w = threadIdx.x >> 5;
    if (lane==0) sh[w] = v;
    __syncthreads();
    int nw = blockDim.x >> 5;
    float r = -3.402823466e38f;
#pragma unroll 8
    for (int i=0;i<nw;i++) if (i < nw) r = fmaxf(r, sh[i]);
    return r;
}

// ---------------- helpers -------------
__device__ __forceinline__ unsigned f2tf32(float x){
    unsigned r; asm("cvt.rna.tf32.f32 %0, %1;" : "=r"(r) : "f"(x)); return r;
}
__device__ __forceinline__ float tf32f(float x){
    return __uint_as_float(f2tf32(x));
}
__device__ __forceinline__ void ldsm4(unsigned* d, const float* p){
    unsigned a = (unsigned)__cvta_generic_to_shared(p);
    asm volatile("ldmatrix.sync.aligned.m8n8.x4.shared.b16 {%0,%1,%2,%3}, [%4];"
                 : "=r"(d[0]),"=r"(d[1]),"=r"(d[2]),"=r"(d[3]) : "r"(a));
}
__device__ __forceinline__ void mma_tf32(float* c, const unsigned* a, unsigned b0, unsigned b1){
    asm volatile("mma.sync.aligned.m16n8k8.row.col.f32.tf32.tf32.f32 "
                 "{%0,%1,%2,%3}, {%4,%5,%6,%7}, {%8,%9}, {%0,%1,%2,%3};"
                 : "+f"(c[0]),"+f"(c[1]),"+f"(c[2]),"+f"(c[3])
                 : "r"(a[0]),"r"(a[1]),"r"(a[2]),"r"(a[3]), "r"(b0),"r"(b1));
}
__device__ __forceinline__ float gelu_exact(float x){
    return 0.5f * x * (1.0f + erff(x * 0.70710678118654752f));
}
__device__ __forceinline__ void cpa16(unsigned dst, const void* src){
    asm volatile("cp.async.cg.shared.global [%0], [%1], 16;" :: "r"(dst), "l"(src));
}
__device__ __forceinline__ void cpa_commit(){
    asm volatile("cp.async.commit_group;" ::: "memory");
}
template<int W> __device__ __forceinline__ void cpa_wait(){
    asm volatile("cp.async.wait_group %0;" :: "n"(W) : "memory");
}

// ---------------- LayerNorm (rnd: tf32-round output for GEMM A operands) ----
__global__ void ln_kernel(const float* __restrict__ x, const float* __restrict__ g,
                          const float* __restrict__ b, float* __restrict__ o, int rnd){
    int row = blockIdx.x;
    const float* p = x + (size_t)row*Hc;
    int t = threadIdx.x;
    float v0 = p[t], v1 = p[t+256], v2 = p[t+512];
    float s  = blockSum(v0+v1+v2);
    float m  = s * (1.0f/768.0f);
    float d0 = v0-m, d1 = v1-m, d2 = v2-m;
    float vs = blockSum(d0*d0 + d1*d1 + d2*d2);
    float inv = rsqrtf(vs * (1.0f/768.0f) + 1e-5f);
    float* q = o + (size_t)row*Hc;
    float r0 = d0*inv*g[t]     + b[t];
    float r1 = d1*inv*g[t+256] + b[t+256];
    float r2 = d2*inv*g[t+512] + b[t+512];
    if (rnd){ r0 = tf32f(r0); r1 = tf32f(r1); r2 = tf32f(r2); }
    q[t] = r0; q[t+256] = r1; q[t+512] = r2;
}

// ---------------- weight transpose + tf32 round: out[noff+n][k] = rna(in[k][n]) ----
__global__ void transpose_w(const float* __restrict__ in, float* __restrict__ out,
                            int K, int N, int noff, int OS,
                            size_t inL, size_t outL){
    __shared__ float t[32][33];
    int l = blockIdx.z;
    in  += (size_t)l*inL;
    out += (size_t)l*outL;
    int nb = blockIdx.x*32, kb = blockIdx.y*32;
    int tx = threadIdx.x, ty = threadIdx.y;   // 32 x 8
#pragma unroll
    for (int j=0;j<4;j++)
        t[ty+j*8][tx] = in[(size_t)(kb+ty+j*8)*N + nb+tx];
    __syncthreads();
#pragma unroll
    for (int j=0;j<4;j++)
        out[(size_t)(noff+nb+ty+j*8)*OS + kb+tx] = tf32f(t[tx][ty+j*8]);
}

// ---------------- pack qkv bias ----
__global__ void pack_bias(const float* __restrict__ bq, const float* __restrict__ bk,
                          const float* __restrict__ bv, float* __restrict__ o){
    int i = blockIdx.x*256 + threadIdx.x;
    if (i < Lc*QKVS){
        int l = i/QKVS, j = i%QKVS;
        float v = (j<768) ? bq[l*768+j] : (j<1536 ? bk[l*768+j-768] : bv[l*768+j-1536]);
        o[i] = v;
    }
}

// ---------------- cp.async tf32 GEMM: 128x128 tile, K16 chunks, 3 stages ------------
// C[M,N] = A[M,K] @ Bt[N,K]^T + bias  (+GELU+rnd | +residual)
// A rows pre-rounded rna; Bt pre-rounded in transpose_w.
#define PADt 20
#define STGF (128*PADt)         // floats per operand per stage
#define CPG_SMEM (3*2*STGF*4)   // 61440 B
template<int EPI>
__global__ __launch_bounds__(256,2) void cp_gemm(
        const float* __restrict__ A, const float* __restrict__ Bt,
        const float* __restrict__ bias, const float* __restrict__ R,
        float* __restrict__ C, int K, int N){
    extern __shared__ float sms[];
    int tid = threadIdx.x;
    int bm = blockIdx.y*128, bn = blockIdx.x*128;
    int warp = tid>>5, lane = tid&31;
    int wm = (warp>>2)*64, wn = (warp&3)*32;

    // cp.async mapping: 2 ops per thread per operand; id -> (row, 16B-seg)
    int id0 = tid*2, id1 = tid*2+1;
    int r0 = id0>>2, s0g = id0&3, r1 = id1>>2, s1g = id1&3;
    const float* Ap0 = A + (size_t)(bm+r0)*K + s0g*4;
    const float* Ap1 = A + (size_t)(bm+r1)*K + s1g*4;
    const float* Bp0 = Bt + (size_t)(bn+r0)*K + s0g*4;
    const float* Bp1 = Bt + (size_t)(bn+r1)*K + s1g*4;
    unsigned sbase = (unsigned)__cvta_generic_to_shared(sms);
    unsigned oa0 = (r0*PADt + s0g*4)*4, oa1 = (r1*PADt + s1g*4)*4;

    // ldmatrix lane addressing
    int g = lane>>3, lr = lane&7;
    int a_row = wm + lr + (g&1)*8;
    int a_colq = (g>>1)*4;
    int b_row = wn + lr + (g>>1)*8;
    int b_colq = (g&1)*4;

    float acc[16][4];
#pragma unroll
    for (int i=0;i<16;i++){ acc[i][0]=0.f; acc[i][1]=0.f; acc[i][2]=0.f; acc[i][3]=0.f; }

    int nch = K >> 4;
    // prologue: stages 0,1
#pragma unroll
    for (int st=0; st<2; st++){
        unsigned base = sbase + st*(2*STGF*4);
        int k0 = st*16;
        cpa16(base + oa0, Ap0 + k0);
        cpa16(base + oa1, Ap1 + k0);
        cpa16(base + STGF*4 + oa0, Bp0 + k0);
        cpa16(base + STGF*4 + oa1, Bp1 + k0);
        cpa_commit();
    }

#pragma unroll 1
    for (int it=0; it<nch; ++it){
        int st = it - (it/3)*3;
        if (it+2 < nch) cpa_wait<1>(); else cpa_wait<0>();
        __syncthreads();
        const float* as = sms + st*(2*STGF);
        const float* bs = as + STGF;
#pragma unroll
        for (int kc=0; kc<16; kc+=8){
            unsigned af[4][4];
#pragma unroll
            for (int mt=0; mt<4; mt++)
                ldsm4(af[mt], &as[(a_row + mt*16)*PADt + kc + a_colq]);
            unsigned bf[2][4];
#pragma unroll
            for (int np=0; np<2; np++)
                ldsm4(bf[np], &bs[(b_row + np*16)*PADt + kc + b_colq]);
#pragma unroll
            for (int mt=0; mt<4; mt++)
#pragma unroll
                for (int nt=0; nt<4; nt++)
                    mma_tf32(acc[mt*4+nt], af[mt], bf[nt>>1][(nt&1)*2], bf[nt>>1][(nt&1)*2+1]);
        }
        if (it+2 < nch){
            int st2 = (it+2) - ((it+2)/3)*3;
            unsigned base = sbase + st2*(2*STGF*4);
            int k0 = (it+2)*16;
            cpa16(base + oa0, Ap0 + k0);
            cpa16(base + oa1, Ap1 + k0);
            cpa16(base + STGF*4 + oa0, Bp0 + k0);
            cpa16(base + STGF*4 + oa1, Bp1 + k0);
            cpa_commit();
        }
    }

    // epilogue
    int cr = lane>>2, cc = (lane&3)*2;
#pragma unroll
    for (int nt=0; nt<4; nt++){
        int col = bn + wn + nt*8 + cc;
        float2 bv = *(const float2*)(bias + col);
#pragma unroll
        for (int mt=0; mt<4; mt++){
            int row0 = bm + wm + mt*16 + cr;
            float* a4 = acc[mt*4+nt];
#pragma unroll
            for (int half=0; half<2; half++){
                int row = row0 + half*8;
                float2 r;
                r.x = a4[half*2+0] + bv.x;
                r.y = a4[half*2+1] + bv.y;
                if (EPI==1){
                    r.x = tf32f(gelu_exact(r.x));   // feeds FFN2 as A: pre-round
                    r.y = tf32f(gelu_exact(r.y));
                }
                if (EPI==2){
                    float2 rr = *(const float2*)(R + (size_t)row*N + col);
                    r.x += rr.x; r.y += rr.y;
                }
                *(float2*)(C + (size_t)row*N + col) = r;
            }
        }
    }
}

// ---------------- tf32 QK^T: 128x128 tile, K=64, fused scale+bias ----
#define PADQ 68
__global__ __launch_bounds__(256,2) void attn_qk_mma(
        const float* __restrict__ q, const float* __restrict__ k,
        const float* __restrict__ bias, float* __restrict__ sc){
    extern __shared__ float sm[];
    float* Qs = sm;                 // [128][PADQ]
    float* Ks = sm + 128*PADQ;      // [128][PADQ]
    int bh = blockIdx.z;
    int b = bh / NHc, h = bh % NHc;
    int s0 = blockIdx.y*128, t0 = blockIdx.x*128;
    int tid = threadIdx.x;
    int warp = tid>>5, lane = tid&31;
    int wm = (warp>>2)*64, wn = (warp&3)*32;

    {
        int row = tid>>1, cb = (tid&1)*32;
        const float* qp = q + (size_t)(b*Sc + s0 + row)*QKVS + h*Dc + cb;
        const float* kp = k + (size_t)(b*Sc + t0 + row)*QKVS + h*Dc + cb;
        float* dq = &Qs[row*PADQ + cb];
        float* dk = &Ks[row*PADQ + cb];
#pragma unroll
        for (int z=0; z<8; z++){
            float4 a = *(const float4*)(qp + z*4);
            dq[z*4+0]=tf32f(a.x); dq[z*4+1]=tf32f(a.y);
            dq[z*4+2]=tf32f(a.z); dq[z*4+3]=tf32f(a.w);
            float4 c = *(const float4*)(kp + z*4);
            dk[z*4+0]=tf32f(c.x); dk[z*4+1]=tf32f(c.y);
            dk[z*4+2]=tf32f(c.z); dk[z*4+3]=tf32f(c.w);
        }
    }
    __syncthreads();

    int g = lane>>3, lr = lane&7;
    int a_row = wm + lr + (g&1)*8;
    int a_colq = (g>>1)*4;
    int b_row = wn + lr + (g>>1)*8;
    int b_colq = (g&1)*4;

    float acc[16][4];
#pragma unroll
    for (int i=0;i<16;i++){ acc[i][0]=0.f; acc[i][1]=0.f; acc[i][2]=0.f; acc[i][3]=0.f; }

#pragma unroll
    for (int kc=0; kc<64; kc+=8){
        unsigned af[4][4];
#pragma unroll
        for (int mt=0; mt<4; mt++)
            ldsm4(af[mt], &Qs[(a_row + mt*16)*PADQ + kc + a_colq]);
        unsigned bf[2][4];
#pragma unroll
        for (int np=0; np<2; np++)
            ldsm4(bf[np], &Ks[(b_row + np*16)*PADQ + kc + b_colq]);
#pragma unroll
        for (int mt=0; mt<4; mt++)
#pragma unroll
            for (int nt=0; nt<4; nt++)
                mma_tf32(acc[mt*4+nt], af[mt], bf[nt>>1][(nt&1)*2], bf[nt>>1][(nt&1)*2+1]);
    }

    int cr = lane>>2, cc = (lane&3)*2;
#pragma unroll
    for (int nt=0; nt<4; nt++){
        int tcol = t0 + wn + nt*8 + cc;
#pragma unroll
        for (int mt=0; mt<4; mt++){
            float* a4 = acc[mt*4+nt];
#pragma unroll
            for (int half=0; half<2; half++){
                int srow = s0 + wm + mt*16 + cr + half*8;
                size_t idx = ((size_t)bh*Sc + srow)*Sc + tcol;
                float2 bi = *(const float2*)(bias + idx);
                float2 r;
                r.x = fmaf(a4[half*2+0], 0.125f, bi.x);
                r.y = fmaf(a4[half*2+1], 0.125f, bi.y);
                *(float2*)(sc + idx) = r;
            }
        }
    }
}

// ---------------- softmax -------------
__global__ void softmax_kernel(float* __restrict__ sc){
    size_t row = blockIdx.x;
    float* p = sc + row*Sc;
    int t = threadIdx.x;
    float v[4];
#pragma unroll
    for (int i=0;i<4;i++) v[i] = p[t + i*128];
    float mx = fmaxf(fmaxf(v[0],v[1]), fmaxf(v[2],v[3]));
    mx = blockMax(mx);
    float s = 0.f;
#pragma unroll
    for (int i=0;i<4;i++){ v[i] = __expf(v[i]-mx); s += v[i]; }
    s = blockSum(s);
    float r = 1.0f / s;
#pragma unroll
    for (int i=0;i<4;i++) p[t + i*128] = v[i]*r;
}

// ---------------- tf32 A@V: 128(s) x 64(d), K=512 in chunks of 64 ----
__global__ __launch_bounds__(256,2) void attn_av_mma(
        const float* __restrict__ sc, const float* __restrict__ v,
        float* __restrict__ o){
    extern __shared__ float sm[];
    float* As = sm;                 // [128][PADQ]
    float* Vs = sm + 128*PADQ;      // [64][PADQ]
    int bh = blockIdx.y;
    int b = bh / NHc, h = bh % NHc;
    int s0 = blockIdx.x*128;
    int tid = threadIdx.x;
    int warp = tid>>5, lane = tid&31;
    int wm = (warp>>1)*32, wn = (warp&1)*32;

    int g = lane>>3, lr = lane&7;
    int a_row = wm + lr + (g&1)*8;
    int a_colq = (g>>1)*4;
    int b_row = wn + lr + (g>>1)*8;
    int b_colq = (g&1)*4;

    float acc[8][4];
#pragma unroll
    for (int i=0;i<8;i++){ acc[i][0]=0.f; acc[i][1]=0.f; acc[i][2]=0.f; acc[i][3]=0.f; }

    int prow = tid>>1, pcb = (tid&1)*32;
    int vt = tid>>2, vdb = (tid&3)*16;

    for (int t0c=0; t0c<Sc; t0c+=64){
        const float* pp = sc + ((size_t)bh*Sc + (s0+prow))*Sc + t0c + pcb;
        const float* vp = v + (size_t)(b*Sc + t0c + vt)*QKVS + h*Dc + vdb;
        float4 pv[8], vv[4];
#pragma unroll
        for (int z=0; z<8; z++) pv[z] = *(const float4*)(pp + z*4);
#pragma unroll
        for (int z=0; z<4; z++) vv[z] = *(const float4*)(vp + z*4);
        __syncthreads();
        float* dp = &As[prow*PADQ + pcb];
#pragma unroll
        for (int z=0; z<8; z++){
            dp[z*4+0]=tf32f(pv[z].x); dp[z*4+1]=tf32f(pv[z].y);
            dp[z*4+2]=tf32f(pv[z].z); dp[z*4+3]=tf32f(pv[z].w);
        }
#pragma unroll
        for (int z=0; z<4; z++){
            Vs[(vdb+z*4+0)*PADQ + vt]=tf32f(vv[z].x);
            Vs[(vdb+z*4+1)*PADQ + vt]=tf32f(vv[z].y);
            Vs[(vdb+z*4+2)*PADQ + vt]=tf32f(vv[z].z);
            Vs[(vdb+z*4+3)*PADQ + vt]=tf32f(vv[z].w);
        }
        __syncthreads();
#pragma unroll
        for (int kc=0; kc<64; kc+=8){
            unsigned af[2][4];
#pragma unroll
            for (int mt=0; mt<2; mt++)
                ldsm4(af[mt], &As[(a_row + mt*16)*PADQ + kc + a_colq]);
            unsigned bf[2][4];
#pragma unroll
            for (int np=0; np<2; np++)
                ldsm4(bf[np], &Vs[(b_row + np*16)*PADQ + kc + b_colq]);
#pragma unroll
            for (int mt=0; mt<2; mt++)
#pragma unroll
                for (int nt=0; nt<4; nt++)
                    mma_tf32(acc[mt*4+nt], af[mt], bf[nt>>1][(nt&1)*2], bf[nt>>1][(nt&1)*2+1]);
        }
    }

    int cr = lane>>2, cc = (lane&3)*2;
#pragma unroll
    for (int nt=0; nt<4; nt++){
        int dcol = wn + nt*8 + cc;
#pragma unroll
        for (int mt=0; mt<2; mt++){
            float* a4 = acc[mt*4+nt];
#pragma unroll
            for (int half=0; half<2; half++){
                int srow = s0 + wm + mt*16 + cr + half*8;
                float2 r;
                r.x = tf32f(a4[half*2+0]);      // feeds Wo GEMM as A: pre-round
                r.y = tf32f(a4[half*2+1]);
                *(float2*)(o + ((size_t)(b*Sc + srow)*NHc + h)*Dc + dcol) = r;
            }
        }
    }
}

// ---------------- launch -------------
extern "C" void kernel_launch(void* const* d_in, const int* in_sizes, int n_in,
                              void* d_out, int out_size){
    const float* x    = (const float*)d_in[0];
    const float* ab   = (const float*)d_in[1];
    const float* ln1g = (const float*)d_in[2];
    const float* ln1b = (const float*)d_in[3];
    const float* wq   = (const float*)d_in[4];
    const float* bq   = (const float*)d_in[5];
    const float* wk   = (const float*)d_in[6];
    const float* bk   = (const float*)d_in[7];
    const float* wv   = (const float*)d_in[8];
    const float* bv   = (const float*)d_in[9];
    const float* wo   = (const float*)d_in[10];
    const float* bo   = (const float*)d_in[11];
    const float* ln2g = (const float*)d_in[12];
    const float* ln2b = (const float*)d_in[13];
    const float* w1   = (const float*)d_in[14];
    const float* b1   = (const float*)d_in[15];
    const float* w2   = (const float*)d_in[16];
    const float* b2   = (const float*)d_in[17];
    const float* flng = (const float*)d_in[18];
    const float* flnb = (const float*)d_in[19];

    float *ph, *py, *pao, *psc, *pff, *pwqkv, *pwo, *pw1, *pw2, *pbqkv;
    cudaGetSymbolAddress((void**)&ph,   g_h);
    cudaGetSymbolAddress((void**)&py,   g_y);
    cudaGetSymbolAddress((void**)&pao,  g_ao);
    cudaGetSymbolAddress((void**)&psc,  g_sc);
    cudaGetSymbolAddress((void**)&pff,  g_ff);
    cudaGetSymbolAddress((void**)&pwqkv,g_wqkvT);
    cudaGetSymbolAddress((void**)&pwo,  g_woT);
    cudaGetSymbolAddress((void**)&pw1,  g_w1T);
    cudaGetSymbolAddress((void**)&pw2,  g_w2T);
    cudaGetSymbolAddress((void**)&pbqkv,g_bqkv);

    static int smem_set = 0;
    const int qk_smem = 2*128*PADQ*sizeof(float);          // 69632
    const int av_smem = (128+64)*PADQ*sizeof(float);       // 52224
    if (!smem_set){
        cudaFuncSetAttribute(attn_qk_mma, cudaFuncAttributeMaxDynamicSharedMemorySize, qk_smem);
        cudaFuncSetAttribute(attn_av_mma, cudaFuncAttributeMaxDynamicSharedMemorySize, av_smem);
        cudaFuncSetAttribute(cp_gemm<0>, cudaFuncAttributeMaxDynamicSharedMemorySize, CPG_SMEM);
        cudaFuncSetAttribute(cp_gemm<1>, cudaFuncAttributeMaxDynamicSharedMemorySize, CPG_SMEM);
        cudaFuncSetAttribute(cp_gemm<2>, cudaFuncAttributeMaxDynamicSharedMemorySize, CPG_SMEM);
        smem_set = 1;
    }

    cudaMemcpyAsync(ph, x, (size_t)Mrows*Hc*sizeof(float), cudaMemcpyDeviceToDevice, 0);

    // ---- weight prep: transpose + tf32-round (+ bias pack) ----
    dim3 tb(32,8);
    transpose_w<<<dim3(Hc/32, Hc/32, Lc), tb>>>(wq, pwqkv, Hc, Hc, 0,    Hc, (size_t)Hc*Hc, (size_t)QKVS*Hc);
    transpose_w<<<dim3(Hc/32, Hc/32, Lc), tb>>>(wk, pwqkv, Hc, Hc, 768,  Hc, (size_t)Hc*Hc, (size_t)QKVS*Hc);
    transpose_w<<<dim3(Hc/32, Hc/32, Lc), tb>>>(wv, pwqkv, Hc, Hc, 1536, Hc, (size_t)Hc*Hc, (size_t)QKVS*Hc);
    transpose_w<<<dim3(Hc/32, Hc/32, Lc), tb>>>(wo, pwo,   Hc, Hc, 0,    Hc, (size_t)Hc*Hc, (size_t)Hc*Hc);
    transpose_w<<<dim3(FFc/32, Hc/32, Lc), tb>>>(w1, pw1,  Hc, FFc, 0,   Hc, (size_t)Hc*FFc, (size_t)FFc*Hc);
    transpose_w<<<dim3(Hc/32, FFc/32, Lc), tb>>>(w2, pw2,  FFc, Hc, 0,  FFc, (size_t)FFc*Hc, (size_t)Hc*FFc);
    pack_bias<<<(Lc*QKVS+255)/256, 256>>>(bq, bk, bv, pbqkv);

    dim3 gqkv(QKVS/128, Mrows/128);     // 18 x 64
    dim3 gproj(Hc/128, Mrows/128);      // 6 x 64
    dim3 gffn1(FFc/128, Mrows/128);     // 24 x 64
    dim3 gqk(4, 4, BHc);
    dim3 gav(4, BHc);

    for (int l=0; l<Lc; l++){
        ln_kernel<<<Mrows, 256>>>(ph, ln1g + l*Hc, ln1b + l*Hc, py, 1);
        cp_gemm<0><<<gqkv, 256, CPG_SMEM>>>(py, pwqkv + (size_t)l*QKVS*Hc, pbqkv + l*QKVS,
                                            nullptr, pff, Hc, QKVS);
        attn_qk_mma<<<gqk, 256, qk_smem>>>(pff, pff + 768, ab, psc);
        softmax_kernel<<<BHc*Sc, 128>>>(psc);
        attn_av_mma<<<gav, 256, av_smem>>>(psc, pff + 1536, pao);
        cp_gemm<2><<<gproj, 256, CPG_SMEM>>>(pao, pwo + (size_t)l*Hc*Hc, bo + l*Hc,
                                             ph, ph, Hc, Hc);
        ln_kernel<<<Mrows, 256>>>(ph, ln2g + l*Hc, ln2b + l*Hc, py, 1);
        cp_gemm<1><<<gffn1, 256, CPG_SMEM>>>(py, pw1 + (size_t)l*FFc*Hc, b1 + l*FFc,
                                             nullptr, pff, Hc, FFc);
        cp_gemm<2><<<gproj, 256, CPG_SMEM>>>(pff, pw2 + (size_t)l*Hc*FFc, b2 + l*Hc,
                                             ph, ph, FFc, Hc);
    }
    ln_kernel<<<Mrows, 256>>>(ph, flng, flnb, (float*)d_out, 0);
}